// round 1
// baseline (speedup 1.0000x reference)
#include <cuda_runtime.h>

// ContrastiveCosineLoss via feature-space Gram trick:
//   answer = (||Xf^T Xf||_F^2 - 2||Xr^T Xf||_F^2 + ||Xr^T Xr||_F^2) / (N*(N-1))
// with Y = [Xr | Xf] (row-normalized), computed as one signed SYRK:
//   numerator = sum_{k,l} s_k s_l (Y^T Y)_{kl}^2,  s_k = -1 for reduced cols, +1 for full.

#define N_SAMPLES 2048
#define D_RED     128
#define D_FULL    1024
#define D_TOT     1152
#define TILE      64
#define NT        (D_TOT / TILE)          // 18
#define NTILES    (NT * (NT + 1) / 2)     // 171 upper-triangular tiles
#define KT        32

__device__ float g_Y[N_SAMPLES * D_TOT];  // normalized [Xr | Xf], row-major
__device__ float g_part[NTILES];          // per-tile partial sums

// ---------------------------------------------------------------------------
// Kernel 1: row-normalize both inputs into g_Y (one block per sample row)
// ---------------------------------------------------------------------------
__global__ void normalize_kernel(const float* __restrict__ red,
                                 const float* __restrict__ full) {
    int row = blockIdx.x;
    int t = threadIdx.x;  // 256 threads
    const float* r = red  + row * D_RED;
    const float* f = full + row * D_FULL;

    float sr = 0.f, sf = 0.f;
    for (int k = t; k < D_RED;  k += 256) { float v = r[k]; sr += v * v; }
    for (int k = t; k < D_FULL; k += 256) { float v = f[k]; sf += v * v; }

    __shared__ float s1[256], s2[256];
    s1[t] = sr; s2[t] = sf;
    __syncthreads();
    #pragma unroll
    for (int o = 128; o > 0; o >>= 1) {
        if (t < o) { s1[t] += s1[t + o]; s2[t] += s2[t + o]; }
        __syncthreads();
    }
    float inv_r = 1.f / fmaxf(sqrtf(s1[0]), 1e-8f);
    float inv_f = 1.f / fmaxf(sqrtf(s2[0]), 1e-8f);

    float* y = g_Y + row * D_TOT;
    for (int k = t; k < D_RED;  k += 256) y[k]         = r[k] * inv_r;
    for (int k = t; k < D_FULL; k += 256) y[D_RED + k] = f[k] * inv_f;
}

// ---------------------------------------------------------------------------
// Kernel 2: signed-square SYRK over upper-triangular 64x64 tiles of Y^T Y.
// Each block computes one G tile (K-loop over 2048 samples), then reduces
// sum(s_k * s_l * G^2) for its tile. Off-diagonal tiles count twice.
// ---------------------------------------------------------------------------
__global__ void __launch_bounds__(256, 2) gram_kernel() {
    int b = blockIdx.x;
    // triangular index -> (tk, tl), tk <= tl
    int tk = 0, rem = b, rowlen = NT;
    while (rem >= rowlen) { rem -= rowlen; tk++; rowlen--; }
    int tl = tk + rem;

    __shared__ float As[KT][TILE + 4];
    __shared__ float Bs[KT][TILE + 4];

    int t  = threadIdx.x;
    int tx = t & 15;        // column group (4 cols)
    int ty = t >> 4;        // row group (4 rows)

    float acc[4][4] = {};

    const int ca = tk * TILE;   // feature cols for the "k" side
    const int cb = tl * TILE;   // feature cols for the "l" side

    for (int k0 = 0; k0 < N_SAMPLES; k0 += KT) {
        // Load KT x TILE slabs of both column groups (float4, coalesced).
        #pragma unroll
        for (int j = 0; j < 2; j++) {
            int idx = t + 256 * j;       // 0..511
            int rr = idx >> 4;           // sample row within slab, 0..31
            int cv = (idx & 15) << 2;    // col offset 0,4,...,60
            const float* src = g_Y + (size_t)(k0 + rr) * D_TOT;
            float4 va = *reinterpret_cast<const float4*>(src + ca + cv);
            float4 vb = *reinterpret_cast<const float4*>(src + cb + cv);
            *reinterpret_cast<float4*>(&As[rr][cv]) = va;
            *reinterpret_cast<float4*>(&Bs[rr][cv]) = vb;
        }
        __syncthreads();

        #pragma unroll
        for (int kk = 0; kk < KT; kk++) {
            float a[4], bb[4];
            *reinterpret_cast<float4*>(a)  = *reinterpret_cast<const float4*>(&As[kk][ty << 2]);
            *reinterpret_cast<float4*>(bb) = *reinterpret_cast<const float4*>(&Bs[kk][tx << 2]);
            #pragma unroll
            for (int i = 0; i < 4; i++)
                #pragma unroll
                for (int jj = 0; jj < 4; jj++)
                    acc[i][jj] += a[i] * bb[jj];
        }
        __syncthreads();
    }

    // Signed square reduction for this tile.
    float sum = 0.f;
    #pragma unroll
    for (int i = 0; i < 4; i++) {
        int kidx = ca + (ty << 2) + i;
        float sk = (kidx < D_RED) ? -1.f : 1.f;
        #pragma unroll
        for (int jj = 0; jj < 4; jj++) {
            int lidx = cb + (tx << 2) + jj;
            float sl = (lidx < D_RED) ? -1.f : 1.f;
            float g = acc[i][jj];
            sum += sk * sl * g * g;
        }
    }
    if (tk != tl) sum *= 2.f;   // symmetry: off-diagonal tiles appear twice

    __shared__ float sred[256];
    sred[t] = sum;
    __syncthreads();
    #pragma unroll
    for (int o = 128; o > 0; o >>= 1) {
        if (t < o) sred[t] += sred[t + o];
        __syncthreads();
    }
    if (t == 0) g_part[b] = sred[0];
}

// ---------------------------------------------------------------------------
// Kernel 3: deterministic final reduction + scaling.
// ---------------------------------------------------------------------------
__global__ void finalize_kernel(float* __restrict__ out) {
    __shared__ float s[256];
    int t = threadIdx.x;
    float v = 0.f;
    for (int i = t; i < NTILES; i += 256) v += g_part[i];
    s[t] = v;
    __syncthreads();
    #pragma unroll
    for (int o = 128; o > 0; o >>= 1) {
        if (t < o) s[t] += s[t + o];
        __syncthreads();
    }
    if (t == 0)
        out[0] = s[0] / ((float)N_SAMPLES * (float)(N_SAMPLES - 1));
}

// ---------------------------------------------------------------------------
extern "C" void kernel_launch(void* const* d_in, const int* in_sizes, int n_in,
                              void* d_out, int out_size) {
    // Defensive input-order resolution: reduced is 2048*128 elements.
    const float* red;
    const float* full;
    if (in_sizes[0] == N_SAMPLES * D_RED) {
        red  = (const float*)d_in[0];
        full = (const float*)d_in[1];
    } else {
        red  = (const float*)d_in[1];
        full = (const float*)d_in[0];
    }

    normalize_kernel<<<N_SAMPLES, 256>>>(red, full);
    gram_kernel<<<NTILES, 256>>>();
    finalize_kernel<<<1, 256>>>((float*)d_out);
}

// round 3
// speedup vs baseline: 3.8705x; 3.8705x over previous
#include <cuda_runtime.h>
#include <cuda_bf16.h>
#include <cstdint>

// ContrastiveCosineLoss via signed feature-Gram SYRK on warp-level bf16 MMA:
//   numerator = sum_{k,l} s_k s_l (Y^T Y)_{kl}^2, Y = [Xr | Xf] row-normalized,
//   s = -1 for reduced feature cols, +1 for full. answer = numerator / (N*(N-1)).
// (tcgen05 PTX is rejected by this harness's compute_103 base target; use
//  arch-portable mma.sync/ldmatrix/cp.async which still hit the tensor pipe.)

#define N_SAMPLES 2048
#define D_RED     128
#define D_FULL    1024
#define D_TOT     1152                 // 18 * 64
#define TILE      64
#define NT        (D_TOT / TILE)       // 18
#define NTILES    (NT * (NT + 1) / 2)  // 171
#define CHUNK     64                   // samples per K-chunk
#define NCHUNK    (N_SAMPLES / CHUNK)  // 32
#define PITCH     72                   // bf16 elements per SMEM row (bank-safe)

__device__ __align__(4096) __nv_bfloat16 g_Yb[N_SAMPLES * D_TOT]; // row-major normalized
__device__ __align__(4096) __nv_bfloat16 g_Yt[D_TOT * N_SAMPLES]; // feature-major
__device__ float g_part[NTILES];

// ---------------------------------------------------------------------------
__device__ __forceinline__ uint32_t smem_u32(const void* p) {
    uint32_t a;
    asm("{ .reg .u64 t; cvta.to.shared.u64 t, %1; cvt.u32.u64 %0, t; }" : "=r"(a) : "l"(p));
    return a;
}
__device__ __forceinline__ void cp16(uint32_t sdst, const void* g) {
    asm volatile("cp.async.cg.shared.global [%0], [%1], 16;" :: "r"(sdst), "l"(g) : "memory");
}
__device__ __forceinline__ void ldsm_x4(uint32_t* r, uint32_t addr) {
    asm volatile("ldmatrix.sync.aligned.m8n8.x4.shared.b16 {%0,%1,%2,%3}, [%4];"
                 : "=r"(r[0]), "=r"(r[1]), "=r"(r[2]), "=r"(r[3]) : "r"(addr));
}
__device__ __forceinline__ void mma_bf16(float* c, const uint32_t* a, uint32_t b0, uint32_t b1) {
    asm volatile(
        "mma.sync.aligned.m16n8k16.row.col.f32.bf16.bf16.f32 "
        "{%0,%1,%2,%3}, {%4,%5,%6,%7}, {%8,%9}, {%0,%1,%2,%3};"
        : "+f"(c[0]), "+f"(c[1]), "+f"(c[2]), "+f"(c[3])
        : "r"(a[0]), "r"(a[1]), "r"(a[2]), "r"(a[3]), "r"(b0), "r"(b1));
}

// ---------------------------------------------------------------------------
// Kernel 1: row-normalize -> bf16 row-major. One warp per sample row.
// ---------------------------------------------------------------------------
__global__ void __launch_bounds__(256) normalize_kernel(const float* __restrict__ red,
                                                        const float* __restrict__ full) {
    int t = threadIdx.x, lane = t & 31, wid = t >> 5;
    int row = blockIdx.x * 8 + wid;

    const float4* f4 = (const float4*)(full + (size_t)row * D_FULL);
    const float4* r4 = (const float4*)(red  + (size_t)row * D_RED);

    float4 fv[8];
    #pragma unroll
    for (int j = 0; j < 8; j++) fv[j] = f4[lane + 32 * j];
    float4 rv = r4[lane];

    float sf = 0.f;
    #pragma unroll
    for (int j = 0; j < 8; j++)
        sf += fv[j].x * fv[j].x + fv[j].y * fv[j].y + fv[j].z * fv[j].z + fv[j].w * fv[j].w;
    float sr = rv.x * rv.x + rv.y * rv.y + rv.z * rv.z + rv.w * rv.w;

    #pragma unroll
    for (int o = 16; o > 0; o >>= 1) {
        sf += __shfl_xor_sync(0xFFFFFFFFu, sf, o);
        sr += __shfl_xor_sync(0xFFFFFFFFu, sr, o);
    }
    float iff = 1.f / fmaxf(sqrtf(sf), 1e-8f);
    float ir  = 1.f / fmaxf(sqrtf(sr), 1e-8f);

    // reduced block: 128 bf16 = 32 lanes x 8B
    {
        __nv_bfloat162 h0 = __floats2bfloat162_rn(rv.x * ir, rv.y * ir);
        __nv_bfloat162 h1 = __floats2bfloat162_rn(rv.z * ir, rv.w * ir);
        uint2 v = make_uint2(*(uint32_t*)&h0, *(uint32_t*)&h1);
        ((uint2*)(g_Yb + (size_t)row * D_TOT))[lane] = v;
    }
    // full block
    uint2* dst = (uint2*)(g_Yb + (size_t)row * D_TOT + D_RED);
    #pragma unroll
    for (int j = 0; j < 8; j++) {
        __nv_bfloat162 h0 = __floats2bfloat162_rn(fv[j].x * iff, fv[j].y * iff);
        __nv_bfloat162 h1 = __floats2bfloat162_rn(fv[j].z * iff, fv[j].w * iff);
        dst[lane + 32 * j] = make_uint2(*(uint32_t*)&h0, *(uint32_t*)&h1);
    }
}

// ---------------------------------------------------------------------------
// Kernel 2: transpose g_Yb [2048,1152] -> g_Yt [1152,2048] (64x64 bf16 tiles)
// ---------------------------------------------------------------------------
__global__ void __launch_bounds__(256) transpose_kernel() {
    __shared__ unsigned short tile[64][66];
    int t = threadIdx.x;
    int f0 = blockIdx.x * 64, i0 = blockIdx.y * 64;
    const unsigned short* Yb = (const unsigned short*)g_Yb;
    unsigned short* Yt = (unsigned short*)g_Yt;

    #pragma unroll
    for (int j = 0; j < 8; j++) {
        int lin = t + 256 * j;          // 0..2047
        int r = lin >> 5, cu = lin & 31;
        uint32_t v = *(const uint32_t*)(Yb + (size_t)(i0 + r) * D_TOT + f0 + cu * 2);
        *(uint32_t*)&tile[r][cu * 2] = v;
    }
    __syncthreads();
    #pragma unroll
    for (int j = 0; j < 8; j++) {
        int lin = t + 256 * j;
        int fr = lin >> 5, cu = lin & 31;
        uint32_t lo = tile[cu * 2][fr];
        uint32_t hi = tile[cu * 2 + 1][fr];
        *(uint32_t*)(Yt + (size_t)(f0 + fr) * N_SAMPLES + i0 + cu * 2) = lo | (hi << 16);
    }
}

// ---------------------------------------------------------------------------
// Kernel 3: bf16 warp-MMA SYRK tile + signed-square reduce. 171 CTAs, 256 thr.
// ---------------------------------------------------------------------------
__global__ void __launch_bounds__(256, 1) gram_kernel() {
    __shared__ __align__(16) __nv_bfloat16 As[2][TILE][PITCH];
    __shared__ __align__(16) __nv_bfloat16 Bs[2][TILE][PITCH];
    __shared__ float sred[8];

    int t = threadIdx.x, lane = t & 31, wid = t >> 5;

    // triangular tile index -> (a, b2), a <= b2
    int blk = blockIdx.x;
    int a = 0, rem = blk, rl = NT;
    while (rem >= rl) { rem -= rl; a++; rl--; }
    int b2 = a + rem;
    bool diag = (a == b2);

    const __nv_bfloat16* Abase = g_Yt + (size_t)a  * TILE * N_SAMPLES;
    const __nv_bfloat16* Bbase = g_Yt + (size_t)b2 * TILE * N_SAMPLES;

    auto load_chunk = [&](int s, int c) {
        int k0 = c * CHUNK;
        #pragma unroll
        for (int j = 0; j < 2; j++) {
            int lin = t + 256 * j;       // 0..511
            int row = lin >> 3;          // feature row 0..63
            int v   = lin & 7;           // 16B segment
            cp16(smem_u32(&As[s][row][v * 8]), Abase + (size_t)row * N_SAMPLES + k0 + v * 8);
            cp16(smem_u32(&Bs[s][row][v * 8]), Bbase + (size_t)row * N_SAMPLES + k0 + v * 8);
        }
        asm volatile("cp.async.commit_group;" ::: "memory");
    };

    int m0 = (wid & 1) * 32;   // warp m-offset (2 groups of 32)
    int n0 = (wid >> 1) * 16;  // warp n-offset (4 groups of 16)

    float acc[2][2][4] = {};

    load_chunk(0, 0);

    for (int c = 0; c < NCHUNK; c++) {
        int s = c & 1;
        if (c + 1 < NCHUNK) {
            load_chunk(s ^ 1, c + 1);
            asm volatile("cp.async.wait_group 1;" ::: "memory");
        } else {
            asm volatile("cp.async.wait_group 0;" ::: "memory");
        }
        __syncthreads();

        #pragma unroll
        for (int ks = 0; ks < 4; ks++) {       // 4 x k16 per 64-sample chunk
            int kk = ks * 16;
            int rsel = lane & 15;
            int csel = kk + (lane >> 4) * 8;

            uint32_t af[2][4], bf[4];
            ldsm_x4(af[0], smem_u32(&As[s][m0 + rsel][csel]));
            ldsm_x4(af[1], smem_u32(&As[s][m0 + 16 + rsel][csel]));
            ldsm_x4(bf,    smem_u32(&Bs[s][n0 + rsel][csel]));

            #pragma unroll
            for (int mi = 0; mi < 2; mi++) {
                mma_bf16(acc[mi][0], af[mi], bf[0], bf[2]);
                mma_bf16(acc[mi][1], af[mi], bf[1], bf[3]);
            }
        }
        __syncthreads();
    }

    // signed-square reduction; sign is constant per tile (features <128 = reduced)
    float sum = 0.f;
    #pragma unroll
    for (int mi = 0; mi < 2; mi++)
        #pragma unroll
        for (int ni = 0; ni < 2; ni++)
            #pragma unroll
            for (int q = 0; q < 4; q++) {
                float v = acc[mi][ni][q];
                sum += v * v;
            }
    #pragma unroll
    for (int o = 16; o > 0; o >>= 1)
        sum += __shfl_xor_sync(0xFFFFFFFFu, sum, o);
    if (lane == 0) sred[wid] = sum;
    __syncthreads();
    if (t == 0) {
        float tot = 0.f;
        #pragma unroll
        for (int i = 0; i < 8; i++) tot += sred[i];
        float sp = ((a < 2) != (b2 < 2)) ? -1.f : 1.f;
        float w  = sp * (diag ? 1.f : 2.f);
        g_part[blk] = w * tot;
    }
}

// ---------------------------------------------------------------------------
// Kernel 4: deterministic finalize
// ---------------------------------------------------------------------------
__global__ void finalize_kernel(float* __restrict__ out) {
    __shared__ float s[256];
    int t = threadIdx.x;
    s[t] = (t < NTILES) ? g_part[t] : 0.f;
    __syncthreads();
    #pragma unroll
    for (int o = 128; o > 0; o >>= 1) {
        if (t < o) s[t] += s[t + o];
        __syncthreads();
    }
    if (t == 0)
        out[0] = s[0] / ((float)N_SAMPLES * (float)(N_SAMPLES - 1));
}

// ---------------------------------------------------------------------------
extern "C" void kernel_launch(void* const* d_in, const int* in_sizes, int n_in,
                              void* d_out, int out_size) {
    const float* red;
    const float* full;
    if (in_sizes[0] == N_SAMPLES * D_RED) {
        red  = (const float*)d_in[0];
        full = (const float*)d_in[1];
    } else {
        red  = (const float*)d_in[1];
        full = (const float*)d_in[0];
    }

    normalize_kernel<<<N_SAMPLES / 8, 256>>>(red, full);
    transpose_kernel<<<dim3(D_TOT / 64, N_SAMPLES / 64), 256>>>();
    gram_kernel<<<NTILES, 256>>>();
    finalize_kernel<<<1, 256>>>((float*)d_out);
}

// round 4
// speedup vs baseline: 4.1705x; 1.0775x over previous
#include <cuda_runtime.h>
#include <cuda_bf16.h>
#include <cstdint>

// ContrastiveCosineLoss via signed feature-Gram SYRK on warp-level bf16 MMA:
//   numerator = sum_{k,l} s_k s_l (Y^T Y)_{kl}^2, Y = [Xr | Xf] row-normalized,
//   s = -1 for reduced feature cols (tiles 0,1), +1 for full.
//   answer = numerator / (N*(N-1)).
// Round 4: no transpose kernel (ldmatrix.trans from row-major), finalize fused
// into gram via deterministic last-CTA reduction, 2 CTAs/SM.

#define N_SAMPLES 2048
#define D_RED     128
#define D_FULL    1024
#define D_TOT     1152                 // 18 * 64
#define TILE      64
#define NT        (D_TOT / TILE)       // 18
#define NTILES    (NT * (NT + 1) / 2)  // 171
#define CHUNK     64                   // samples per K-chunk
#define NCHUNK    (N_SAMPLES / CHUNK)  // 32
#define PITCH     72                   // bf16 per SMEM row (144B: LDSM.T bank-safe)

__device__ __align__(4096) __nv_bfloat16 g_Yb[N_SAMPLES * D_TOT]; // row-major normalized
__device__ float g_part[NTILES];
__device__ unsigned int g_count;   // zero-init; reset by last CTA each launch

// ---------------------------------------------------------------------------
__device__ __forceinline__ uint32_t smem_u32(const void* p) {
    uint32_t a;
    asm("{ .reg .u64 t; cvta.to.shared.u64 t, %1; cvt.u32.u64 %0, t; }" : "=r"(a) : "l"(p));
    return a;
}
__device__ __forceinline__ void cp16(uint32_t sdst, const void* g) {
    asm volatile("cp.async.cg.shared.global [%0], [%1], 16;" :: "r"(sdst), "l"(g) : "memory");
}
__device__ __forceinline__ void ldsm_x4_t(uint32_t* r, uint32_t addr) {
    asm volatile("ldmatrix.sync.aligned.m8n8.x4.trans.shared.b16 {%0,%1,%2,%3}, [%4];"
                 : "=r"(r[0]), "=r"(r[1]), "=r"(r[2]), "=r"(r[3]) : "r"(addr));
}
__device__ __forceinline__ void mma_bf16(float* c, const uint32_t* a, uint32_t b0, uint32_t b1) {
    asm volatile(
        "mma.sync.aligned.m16n8k16.row.col.f32.bf16.bf16.f32 "
        "{%0,%1,%2,%3}, {%4,%5,%6,%7}, {%8,%9}, {%0,%1,%2,%3};"
        : "+f"(c[0]), "+f"(c[1]), "+f"(c[2]), "+f"(c[3])
        : "r"(a[0]), "r"(a[1]), "r"(a[2]), "r"(a[3]), "r"(b0), "r"(b1));
}

// ---------------------------------------------------------------------------
// Kernel 1: row-normalize -> bf16 row-major. One warp per sample row.
// ---------------------------------------------------------------------------
__global__ void __launch_bounds__(256) normalize_kernel(const float* __restrict__ red,
                                                        const float* __restrict__ full) {
    int t = threadIdx.x, lane = t & 31, wid = t >> 5;
    int row = blockIdx.x * 8 + wid;

    const float4* f4 = (const float4*)(full + (size_t)row * D_FULL);
    const float4* r4 = (const float4*)(red  + (size_t)row * D_RED);

    float4 fv[8];
    #pragma unroll
    for (int j = 0; j < 8; j++) fv[j] = f4[lane + 32 * j];
    float4 rv = r4[lane];

    float sf = 0.f;
    #pragma unroll
    for (int j = 0; j < 8; j++)
        sf += fv[j].x * fv[j].x + fv[j].y * fv[j].y + fv[j].z * fv[j].z + fv[j].w * fv[j].w;
    float sr = rv.x * rv.x + rv.y * rv.y + rv.z * rv.z + rv.w * rv.w;

    #pragma unroll
    for (int o = 16; o > 0; o >>= 1) {
        sf += __shfl_xor_sync(0xFFFFFFFFu, sf, o);
        sr += __shfl_xor_sync(0xFFFFFFFFu, sr, o);
    }
    float iff = 1.f / fmaxf(sqrtf(sf), 1e-8f);
    float ir  = 1.f / fmaxf(sqrtf(sr), 1e-8f);

    {
        __nv_bfloat162 h0 = __floats2bfloat162_rn(rv.x * ir, rv.y * ir);
        __nv_bfloat162 h1 = __floats2bfloat162_rn(rv.z * ir, rv.w * ir);
        ((uint2*)(g_Yb + (size_t)row * D_TOT))[lane] =
            make_uint2(*(uint32_t*)&h0, *(uint32_t*)&h1);
    }
    uint2* dst = (uint2*)(g_Yb + (size_t)row * D_TOT + D_RED);
    #pragma unroll
    for (int j = 0; j < 8; j++) {
        __nv_bfloat162 h0 = __floats2bfloat162_rn(fv[j].x * iff, fv[j].y * iff);
        __nv_bfloat162 h1 = __floats2bfloat162_rn(fv[j].z * iff, fv[j].w * iff);
        dst[lane + 32 * j] = make_uint2(*(uint32_t*)&h0, *(uint32_t*)&h1);
    }
}

// ---------------------------------------------------------------------------
// Kernel 2: bf16 warp-MMA SYRK tile + signed-square + fused finalize.
// SMEM tiles are [sample][feature]; A/B fragments via ldmatrix.trans.
// ---------------------------------------------------------------------------
__global__ void __launch_bounds__(256, 2) gram_kernel(float* __restrict__ out) {
    __shared__ __align__(16) __nv_bfloat16 As[2][CHUNK][PITCH];
    __shared__ __align__(16) __nv_bfloat16 Bs[2][CHUNK][PITCH];
    __shared__ float sred[8];
    __shared__ unsigned int s_last;

    int t = threadIdx.x, lane = t & 31, wid = t >> 5;

    // triangular tile index -> (a, b2), a <= b2
    int blk = blockIdx.x;
    int a = 0, rem = blk, rl = NT;
    while (rem >= rl) { rem -= rl; a++; rl--; }
    int b2 = a + rem;
    bool diag = (a == b2);

    const __nv_bfloat16* Acol = g_Yb + (size_t)a  * TILE;  // + row*D_TOT
    const __nv_bfloat16* Bcol = g_Yb + (size_t)b2 * TILE;

    auto load_chunk = [&](int s, int c) {
        int k0 = c * CHUNK;
        #pragma unroll
        for (int j = 0; j < 2; j++) {
            int lin = t + 256 * j;       // 0..511
            int row = lin >> 3;          // sample 0..63
            int v   = lin & 7;           // 16B segment (8 bf16)
            const __nv_bfloat16* src = g_Yb + (size_t)(k0 + row) * D_TOT;
            cp16(smem_u32(&As[s][row][v * 8]), src + a  * TILE + v * 8);
            cp16(smem_u32(&Bs[s][row][v * 8]), src + b2 * TILE + v * 8);
        }
        asm volatile("cp.async.commit_group;" ::: "memory");
    };

    int m0 = (wid & 1) * 32;   // warp m-offset within 64
    int n0 = (wid >> 1) * 16;  // warp n-offset within 64

    // ldmatrix.trans lane-address components (same pattern for A and B):
    //  row = kk + (lane&7) + ((lane>>4)&1)*8 ; col = base + ((lane>>3)&1)*8
    int lrow = (lane & 7) + ((lane >> 4) & 1) * 8;
    int lcol = ((lane >> 3) & 1) * 8;

    float acc[2][2][4] = {};

    load_chunk(0, 0);

    for (int c = 0; c < NCHUNK; c++) {
        int s = c & 1;
        if (c + 1 < NCHUNK) {
            load_chunk(s ^ 1, c + 1);
            asm volatile("cp.async.wait_group 1;" ::: "memory");
        } else {
            asm volatile("cp.async.wait_group 0;" ::: "memory");
        }
        __syncthreads();

        #pragma unroll
        for (int ks = 0; ks < 4; ks++) {       // 4 x k16 per 64-sample chunk
            int kk = ks * 16;
            uint32_t af[2][4], bf[4];
            ldsm_x4_t(af[0], smem_u32(&As[s][kk + lrow][m0 + lcol]));
            ldsm_x4_t(af[1], smem_u32(&As[s][kk + lrow][m0 + 16 + lcol]));
            ldsm_x4_t(bf,    smem_u32(&Bs[s][kk + lrow][n0 + lcol]));
            // af regs: a0=(M0K0) a1=(M8K0) a2=(M0K8) a3=(M8K8)  (mma order)
            // bf regs: r0=(K0N0) r1=(K0N8) r2=(K8N0) r3=(K8N8)
            #pragma unroll
            for (int mi = 0; mi < 2; mi++) {
                mma_bf16(acc[mi][0], af[mi], bf[0], bf[2]);
                mma_bf16(acc[mi][1], af[mi], bf[1], bf[3]);
            }
        }
        __syncthreads();
    }

    // signed-square reduction; sign constant per tile (tiles 0,1 = reduced)
    float sum = 0.f;
    #pragma unroll
    for (int mi = 0; mi < 2; mi++)
        #pragma unroll
        for (int ni = 0; ni < 2; ni++)
            #pragma unroll
            for (int q = 0; q < 4; q++) {
                float v = acc[mi][ni][q];
                sum += v * v;
            }
    #pragma unroll
    for (int o = 16; o > 0; o >>= 1)
        sum += __shfl_xor_sync(0xFFFFFFFFu, sum, o);
    if (lane == 0) sred[wid] = sum;
    __syncthreads();
    if (t == 0) {
        float tot = 0.f;
        #pragma unroll
        for (int i = 0; i < 8; i++) tot += sred[i];
        float sp = ((a < 2) != (b2 < 2)) ? -1.f : 1.f;
        float w  = sp * (diag ? 1.f : 2.f);
        g_part[blk] = w * tot;
        __threadfence();
        s_last = (atomicAdd(&g_count, 1u) == NTILES - 1);
    }
    __syncthreads();

    // deterministic fused finalize in the last-arriving CTA
    if (s_last) {
        __shared__ float fs[256];
        float v = (t < NTILES) ? g_part[t] : 0.f;
        fs[t] = v;
        __syncthreads();
        #pragma unroll
        for (int o = 128; o > 0; o >>= 1) {
            if (t < o) fs[t] += fs[t + o];
            __syncthreads();
        }
        if (t == 0) {
            out[0] = fs[0] / ((float)N_SAMPLES * (float)(N_SAMPLES - 1));
            g_count = 0;   // reset for next graph replay
        }
    }
}

// ---------------------------------------------------------------------------
extern "C" void kernel_launch(void* const* d_in, const int* in_sizes, int n_in,
                              void* d_out, int out_size) {
    const float* red;
    const float* full;
    if (in_sizes[0] == N_SAMPLES * D_RED) {
        red  = (const float*)d_in[0];
        full = (const float*)d_in[1];
    } else {
        red  = (const float*)d_in[1];
        full = (const float*)d_in[0];
    }

    normalize_kernel<<<N_SAMPLES / 8, 256>>>(red, full);
    gram_kernel<<<NTILES, 256>>>((float*)d_out);
}

// round 5
// speedup vs baseline: 4.3740x; 1.0488x over previous
#include <cuda_runtime.h>
#include <cuda_bf16.h>
#include <cstdint>

// ContrastiveCosineLoss via signed feature-Gram SYRK on warp-level bf16 MMA:
//   numerator = sum_{k,l} s_k s_l (Y^T Y)_{kl}^2, Y = [Xr | Xf] row-normalized,
//   s = -1 for reduced feature cols (tiles 0,1), +1 for full.
//   answer = numerator / (N*(N-1)).
// Round 5: 3-stage cp.async pipeline, one __syncthreads per chunk, register-
// double-buffered LDSM fragments overlapping MMA.

#define N_SAMPLES 2048
#define D_RED     128
#define D_FULL    1024
#define D_TOT     1152                 // 18 * 64
#define TILE      64
#define NT        (D_TOT / TILE)       // 18
#define NTILES    (NT * (NT + 1) / 2)  // 171
#define CHUNK     64                   // samples per K-chunk
#define NCHUNK    (N_SAMPLES / CHUNK)  // 32
#define PITCH     72                   // bf16 per SMEM row (144B: LDSM.T bank-safe)
#define STAGES    3
#define SLABB     (CHUNK * PITCH * 2)          // 9216 B per operand slab
#define GSMEM     (STAGES * 2 * SLABB)         // 55296 B dynamic smem

__device__ __align__(4096) __nv_bfloat16 g_Yb[N_SAMPLES * D_TOT]; // row-major normalized
__device__ float g_part[NTILES];
__device__ unsigned int g_count;   // zero-init; reset by last CTA each launch

// ---------------------------------------------------------------------------
__device__ __forceinline__ uint32_t smem_u32(const void* p) {
    uint32_t a;
    asm("{ .reg .u64 t; cvta.to.shared.u64 t, %1; cvt.u32.u64 %0, t; }" : "=r"(a) : "l"(p));
    return a;
}
__device__ __forceinline__ void cp16(uint32_t sdst, const void* g) {
    asm volatile("cp.async.cg.shared.global [%0], [%1], 16;" :: "r"(sdst), "l"(g) : "memory");
}
__device__ __forceinline__ void ldsm_x4_t(uint32_t* r, uint32_t addr) {
    asm volatile("ldmatrix.sync.aligned.m8n8.x4.trans.shared.b16 {%0,%1,%2,%3}, [%4];"
                 : "=r"(r[0]), "=r"(r[1]), "=r"(r[2]), "=r"(r[3]) : "r"(addr));
}
__device__ __forceinline__ void mma_bf16(float* c, const uint32_t* a, uint32_t b0, uint32_t b1) {
    asm volatile(
        "mma.sync.aligned.m16n8k16.row.col.f32.bf16.bf16.f32 "
        "{%0,%1,%2,%3}, {%4,%5,%6,%7}, {%8,%9}, {%0,%1,%2,%3};"
        : "+f"(c[0]), "+f"(c[1]), "+f"(c[2]), "+f"(c[3])
        : "r"(a[0]), "r"(a[1]), "r"(a[2]), "r"(a[3]), "r"(b0), "r"(b1));
}

// ---------------------------------------------------------------------------
// Kernel 1: row-normalize -> bf16 row-major. One warp per sample row.
// ---------------------------------------------------------------------------
__global__ void __launch_bounds__(256) normalize_kernel(const float* __restrict__ red,
                                                        const float* __restrict__ full) {
    int t = threadIdx.x, lane = t & 31, wid = t >> 5;
    int row = blockIdx.x * 8 + wid;

    const float4* f4 = (const float4*)(full + (size_t)row * D_FULL);
    const float4* r4 = (const float4*)(red  + (size_t)row * D_RED);

    float4 fv[8];
    #pragma unroll
    for (int j = 0; j < 8; j++) fv[j] = f4[lane + 32 * j];
    float4 rv = r4[lane];

    float sf = 0.f;
    #pragma unroll
    for (int j = 0; j < 8; j++)
        sf += fv[j].x * fv[j].x + fv[j].y * fv[j].y + fv[j].z * fv[j].z + fv[j].w * fv[j].w;
    float sr = rv.x * rv.x + rv.y * rv.y + rv.z * rv.z + rv.w * rv.w;

    #pragma unroll
    for (int o = 16; o > 0; o >>= 1) {
        sf += __shfl_xor_sync(0xFFFFFFFFu, sf, o);
        sr += __shfl_xor_sync(0xFFFFFFFFu, sr, o);
    }
    float iff = 1.f / fmaxf(sqrtf(sf), 1e-8f);
    float ir  = 1.f / fmaxf(sqrtf(sr), 1e-8f);

    {
        __nv_bfloat162 h0 = __floats2bfloat162_rn(rv.x * ir, rv.y * ir);
        __nv_bfloat162 h1 = __floats2bfloat162_rn(rv.z * ir, rv.w * ir);
        ((uint2*)(g_Yb + (size_t)row * D_TOT))[lane] =
            make_uint2(*(uint32_t*)&h0, *(uint32_t*)&h1);
    }
    uint2* dst = (uint2*)(g_Yb + (size_t)row * D_TOT + D_RED);
    #pragma unroll
    for (int j = 0; j < 8; j++) {
        __nv_bfloat162 h0 = __floats2bfloat162_rn(fv[j].x * iff, fv[j].y * iff);
        __nv_bfloat162 h1 = __floats2bfloat162_rn(fv[j].z * iff, fv[j].w * iff);
        dst[lane + 32 * j] = make_uint2(*(uint32_t*)&h0, *(uint32_t*)&h1);
    }
}

// ---------------------------------------------------------------------------
// Kernel 2: bf16 warp-MMA SYRK tile + signed-square + fused finalize.
// SMEM tiles [sample][feature]; fragments via ldmatrix.trans; 3-stage pipeline.
// ---------------------------------------------------------------------------
__global__ void __launch_bounds__(256, 2) gram_kernel(float* __restrict__ out) {
    extern __shared__ __align__(16) char dyn[];
    __shared__ float sred[8];
    __shared__ unsigned int s_last;

    int t = threadIdx.x, lane = t & 31, wid = t >> 5;

    // triangular tile index -> (a, b2), a <= b2
    int blk = blockIdx.x;
    int a = 0, rem = blk, rl = NT;
    while (rem >= rl) { rem -= rl; a++; rl--; }
    int b2 = a + rem;
    bool diag = (a == b2);

    auto slabA = [&](int s) -> __nv_bfloat16* {
        return (__nv_bfloat16*)(dyn + s * 2 * SLABB);
    };
    auto slabB = [&](int s) -> __nv_bfloat16* {
        return (__nv_bfloat16*)(dyn + s * 2 * SLABB + SLABB);
    };

    auto load_chunk = [&](int s, int c) {
        int k0 = c * CHUNK;
        __nv_bfloat16* As = slabA(s);
        __nv_bfloat16* Bs = slabB(s);
        #pragma unroll
        for (int j = 0; j < 2; j++) {
            int lin = t + 256 * j;       // 0..511
            int row = lin >> 3;          // sample 0..63
            int v   = lin & 7;           // 16B segment (8 bf16)
            const __nv_bfloat16* src = g_Yb + (size_t)(k0 + row) * D_TOT;
            cp16(smem_u32(As + row * PITCH + v * 8), src + a  * TILE + v * 8);
            cp16(smem_u32(Bs + row * PITCH + v * 8), src + b2 * TILE + v * 8);
        }
    };

    int m0 = (wid & 1) * 32;   // warp m-offset within 64
    int n0 = (wid >> 1) * 16;  // warp n-offset within 64

    // ldmatrix.trans lane addressing (validated R4):
    int lrow = (lane & 7) + ((lane >> 4) & 1) * 8;
    int lcol = ((lane >> 3) & 1) * 8;

    float acc[2][2][4] = {};

    load_chunk(0, 0);
    asm volatile("cp.async.commit_group;" ::: "memory");
    load_chunk(1, 1);
    asm volatile("cp.async.commit_group;" ::: "memory");

    for (int c = 0; c < NCHUNK; c++) {
        int s = c - (c / STAGES) * STAGES;   // c % 3
        asm volatile("cp.async.wait_group 1;" ::: "memory");
        __syncthreads();

        if (c + 2 < NCHUNK) {
            int s2 = (c + 2) - ((c + 2) / STAGES) * STAGES;
            load_chunk(s2, c + 2);
        }
        asm volatile("cp.async.commit_group;" ::: "memory");

        const __nv_bfloat16* As = slabA(s);
        const __nv_bfloat16* Bs = slabB(s);

        // register-double-buffered fragment pipeline over 4 k16 steps
        uint32_t af[2][2][4], bf[2][4];
        ldsm_x4_t(af[0][0], smem_u32(As + lrow * PITCH + m0 + lcol));
        ldsm_x4_t(af[0][1], smem_u32(As + lrow * PITCH + m0 + 16 + lcol));
        ldsm_x4_t(bf[0],    smem_u32(Bs + lrow * PITCH + n0 + lcol));

        #pragma unroll
        for (int ks = 0; ks < 4; ks++) {
            int cur = ks & 1, nxt = cur ^ 1;
            if (ks < 3) {
                int kk = (ks + 1) * 16;
                ldsm_x4_t(af[nxt][0], smem_u32(As + (kk + lrow) * PITCH + m0 + lcol));
                ldsm_x4_t(af[nxt][1], smem_u32(As + (kk + lrow) * PITCH + m0 + 16 + lcol));
                ldsm_x4_t(bf[nxt],    smem_u32(Bs + (kk + lrow) * PITCH + n0 + lcol));
            }
            #pragma unroll
            for (int mi = 0; mi < 2; mi++) {
                mma_bf16(acc[mi][0], af[cur][mi], bf[cur][0], bf[cur][2]);
                mma_bf16(acc[mi][1], af[cur][mi], bf[cur][1], bf[cur][3]);
            }
        }
    }

    // signed-square reduction; sign constant per tile (tiles 0,1 = reduced)
    float sum = 0.f;
    #pragma unroll
    for (int mi = 0; mi < 2; mi++)
        #pragma unroll
        for (int ni = 0; ni < 2; ni++)
            #pragma unroll
            for (int q = 0; q < 4; q++) {
                float v = acc[mi][ni][q];
                sum += v * v;
            }
    #pragma unroll
    for (int o = 16; o > 0; o >>= 1)
        sum += __shfl_xor_sync(0xFFFFFFFFu, sum, o);
    if (lane == 0) sred[wid] = sum;
    __syncthreads();
    if (t == 0) {
        float tot = 0.f;
        #pragma unroll
        for (int i = 0; i < 8; i++) tot += sred[i];
        float sp = ((a < 2) != (b2 < 2)) ? -1.f : 1.f;
        float w  = sp * (diag ? 1.f : 2.f);
        g_part[blk] = w * tot;
        __threadfence();
        s_last = (atomicAdd(&g_count, 1u) == NTILES - 1);
    }
    __syncthreads();

    // deterministic fused finalize in the last-arriving CTA
    if (s_last) {
        __shared__ float fs[256];
        float v = (t < NTILES) ? g_part[t] : 0.f;
        fs[t] = v;
        __syncthreads();
        #pragma unroll
        for (int o = 128; o > 0; o >>= 1) {
            if (t < o) fs[t] += fs[t + o];
            __syncthreads();
        }
        if (t == 0) {
            out[0] = fs[0] / ((float)N_SAMPLES * (float)(N_SAMPLES - 1));
            g_count = 0;   // reset for next graph replay
        }
    }
}

// ---------------------------------------------------------------------------
extern "C" void kernel_launch(void* const* d_in, const int* in_sizes, int n_in,
                              void* d_out, int out_size) {
    const float* red;
    const float* full;
    if (in_sizes[0] == N_SAMPLES * D_RED) {
        red  = (const float*)d_in[0];
        full = (const float*)d_in[1];
    } else {
        red  = (const float*)d_in[1];
        full = (const float*)d_in[0];
    }

    static int attr_done = 0;
    if (!attr_done) {
        cudaFuncSetAttribute(gram_kernel, cudaFuncAttributeMaxDynamicSharedMemorySize,
                             GSMEM);
        attr_done = 1;
    }

    normalize_kernel<<<N_SAMPLES / 8, 256>>>(red, full);
    gram_kernel<<<NTILES, 256, GSMEM>>>((float*)d_out);
}

// round 6
// speedup vs baseline: 4.7611x; 1.0885x over previous
#include <cuda_runtime.h>
#include <cuda_bf16.h>
#include <cstdint>

// ContrastiveCosineLoss via signed feature-Gram SYRK on warp-level bf16 MMA.
// Round 6: split-K=2 with materialized partial Gram tiles (deterministic),
// separate combine kernel does (g0+g1)^2 reduction; addressing hoisted.

#define N_SAMPLES 2048
#define D_RED     128
#define D_TOT     1152                 // 18 * 64
#define TILE      64
#define NT        (D_TOT / TILE)       // 18
#define NTILES    (NT * (NT + 1) / 2)  // 171
#define NSPLIT    2
#define KSPLIT    (N_SAMPLES / NSPLIT) // 1024
#define CHUNK     64
#define NCHUNK_S  (KSPLIT / CHUNK)     // 16
#define PITCH     72                   // bf16 per SMEM row (144B: LDSM.T bank-safe)
#define STAGES    3
#define SLABB     (CHUNK * PITCH * 2)  // 9216 B per operand slab
#define GSMEM     (STAGES * 2 * SLABB) // 55296 B dynamic smem

__device__ __align__(4096) __nv_bfloat16 g_Yb[N_SAMPLES * D_TOT];
__device__ __align__(4096) float g_G[NSPLIT * NTILES * TILE * TILE]; // partial Gram
__device__ float g_part[NTILES];
__device__ unsigned int g_count;

// ---------------------------------------------------------------------------
__device__ __forceinline__ uint32_t smem_u32(const void* p) {
    uint32_t a;
    asm("{ .reg .u64 t; cvta.to.shared.u64 t, %1; cvt.u32.u64 %0, t; }" : "=r"(a) : "l"(p));
    return a;
}
__device__ __forceinline__ void cp16(uint32_t sdst, const void* g) {
    asm volatile("cp.async.cg.shared.global [%0], [%1], 16;" :: "r"(sdst), "l"(g) : "memory");
}
__device__ __forceinline__ void ldsm_x4_t(uint32_t* r, uint32_t addr) {
    asm volatile("ldmatrix.sync.aligned.m8n8.x4.trans.shared.b16 {%0,%1,%2,%3}, [%4];"
                 : "=r"(r[0]), "=r"(r[1]), "=r"(r[2]), "=r"(r[3]) : "r"(addr));
}
__device__ __forceinline__ void mma_bf16(float* c, const uint32_t* a, uint32_t b0, uint32_t b1) {
    asm volatile(
        "mma.sync.aligned.m16n8k16.row.col.f32.bf16.bf16.f32 "
        "{%0,%1,%2,%3}, {%4,%5,%6,%7}, {%8,%9}, {%0,%1,%2,%3};"
        : "+f"(c[0]), "+f"(c[1]), "+f"(c[2]), "+f"(c[3])
        : "r"(a[0]), "r"(a[1]), "r"(a[2]), "r"(a[3]), "r"(b0), "r"(b1));
}

// ---------------------------------------------------------------------------
// Kernel 1: row-normalize -> bf16 row-major. One warp per sample row.
// ---------------------------------------------------------------------------
__global__ void __launch_bounds__(256) normalize_kernel(const float* __restrict__ red,
                                                        const float* __restrict__ full) {
    int t = threadIdx.x, lane = t & 31, wid = t >> 5;
    int row = blockIdx.x * 8 + wid;

    const float4* f4 = (const float4*)(full + (size_t)row * 1024);
    const float4* r4 = (const float4*)(red  + (size_t)row * D_RED);

    float4 fv[8];
    #pragma unroll
    for (int j = 0; j < 8; j++) fv[j] = f4[lane + 32 * j];
    float4 rv = r4[lane];

    float sf = 0.f;
    #pragma unroll
    for (int j = 0; j < 8; j++)
        sf += fv[j].x * fv[j].x + fv[j].y * fv[j].y + fv[j].z * fv[j].z + fv[j].w * fv[j].w;
    float sr = rv.x * rv.x + rv.y * rv.y + rv.z * rv.z + rv.w * rv.w;

    #pragma unroll
    for (int o = 16; o > 0; o >>= 1) {
        sf += __shfl_xor_sync(0xFFFFFFFFu, sf, o);
        sr += __shfl_xor_sync(0xFFFFFFFFu, sr, o);
    }
    float iff = 1.f / fmaxf(sqrtf(sf), 1e-8f);
    float ir  = 1.f / fmaxf(sqrtf(sr), 1e-8f);

    {
        __nv_bfloat162 h0 = __floats2bfloat162_rn(rv.x * ir, rv.y * ir);
        __nv_bfloat162 h1 = __floats2bfloat162_rn(rv.z * ir, rv.w * ir);
        ((uint2*)(g_Yb + (size_t)row * D_TOT))[lane] =
            make_uint2(*(uint32_t*)&h0, *(uint32_t*)&h1);
    }
    uint2* dst = (uint2*)(g_Yb + (size_t)row * D_TOT + D_RED);
    #pragma unroll
    for (int j = 0; j < 8; j++) {
        __nv_bfloat162 h0 = __floats2bfloat162_rn(fv[j].x * iff, fv[j].y * iff);
        __nv_bfloat162 h1 = __floats2bfloat162_rn(fv[j].z * iff, fv[j].w * iff);
        dst[lane + 32 * j] = make_uint2(*(uint32_t*)&h0, *(uint32_t*)&h1);
    }
}

// ---------------------------------------------------------------------------
// Kernel 2: bf16 warp-MMA partial SYRK tile (K split), writes partial Gram.
// grid = (NTILES, NSPLIT), 256 threads.
// ---------------------------------------------------------------------------
__global__ void __launch_bounds__(256) gram_kernel() {
    extern __shared__ __align__(16) char dyn[];
    int t = threadIdx.x, lane = t & 31, wid = t >> 5;

    int blk = blockIdx.x, split = blockIdx.y;
    int a = 0, rem = blk, rl = NT;
    while (rem >= rl) { rem -= rl; a++; rl--; }
    int b2 = a + rem;

    // ---- hoisted cp.async addressing ----
    int lrowg = t >> 3;            // 0..31 (j=0), +32 for j=1
    int lv    = (t & 7) * 8;       // bf16 offset of 16B segment
    uint32_t sA0 = smem_u32(dyn) + (uint32_t)(lrowg * PITCH + lv) * 2;
    uint32_t sB0 = sA0 + SLABB;
    const uint32_t rowStep = 32 * PITCH * 2;         // j=1 smem offset
    const __nv_bfloat16* gA0 = g_Yb + (size_t)(split * KSPLIT + lrowg) * D_TOT + a * TILE + lv;
    const __nv_bfloat16* gB0 = g_Yb + (size_t)(split * KSPLIT + lrowg) * D_TOT + b2 * TILE + lv;
    const size_t gRow = (size_t)32 * D_TOT;          // j=1 gmem offset
    const size_t gChunk = (size_t)CHUNK * D_TOT;

    auto load_chunk = [&](int s, int c) {
        uint32_t so = (uint32_t)(s * 2 * SLABB);
        const __nv_bfloat16* ga = gA0 + c * gChunk;
        const __nv_bfloat16* gb = gB0 + c * gChunk;
        cp16(sA0 + so,           ga);
        cp16(sA0 + so + rowStep, ga + gRow);
        cp16(sB0 + so,           gb);
        cp16(sB0 + so + rowStep, gb + gRow);
    };

    // ---- hoisted ldmatrix addressing ----
    int m0 = (wid & 1) * 32;
    int n0 = (wid >> 1) * 16;
    int lrow = (lane & 7) + ((lane >> 4) & 1) * 8;
    int lcol = ((lane >> 3) & 1) * 8;
    uint32_t base = smem_u32(dyn);
    uint32_t aA0 = base + (uint32_t)(lrow * PITCH + m0 + lcol) * 2;
    uint32_t aA1 = aA0 + 32;                       // +16 bf16 cols
    uint32_t aB0 = base + SLABB + (uint32_t)(lrow * PITCH + n0 + lcol) * 2;
    const uint32_t kStep = 16 * PITCH * 2;         // +16 k rows

    float acc[2][2][4] = {};

    load_chunk(0, 0);
    asm volatile("cp.async.commit_group;" ::: "memory");
    load_chunk(1, 1);
    asm volatile("cp.async.commit_group;" ::: "memory");

    int s = 0;
    for (int c = 0; c < NCHUNK_S; c++) {
        asm volatile("cp.async.wait_group 1;" ::: "memory");
        __syncthreads();

        if (c + 2 < NCHUNK_S) {
            int s2 = s + 2; if (s2 >= STAGES) s2 -= STAGES;
            load_chunk(s2, c + 2);
        }
        asm volatile("cp.async.commit_group;" ::: "memory");

        uint32_t so = (uint32_t)(s * 2 * SLABB);
        uint32_t af[2][2][4], bf[2][4];
        ldsm_x4_t(af[0][0], aA0 + so);
        ldsm_x4_t(af[0][1], aA1 + so);
        ldsm_x4_t(bf[0],    aB0 + so);

        #pragma unroll
        for (int ks = 0; ks < 4; ks++) {
            int cur = ks & 1, nxt = cur ^ 1;
            if (ks < 3) {
                uint32_t ko = so + (ks + 1) * kStep;
                ldsm_x4_t(af[nxt][0], aA0 + ko);
                ldsm_x4_t(af[nxt][1], aA1 + ko);
                ldsm_x4_t(bf[nxt],    aB0 + ko);
            }
            #pragma unroll
            for (int mi = 0; mi < 2; mi++) {
                mma_bf16(acc[mi][0], af[cur][mi], bf[cur][0], bf[cur][2]);
                mma_bf16(acc[mi][1], af[cur][mi], bf[cur][1], bf[cur][3]);
            }
        }
        if (++s >= STAGES) s -= STAGES;
    }

    // write partial tile, thread-coalesced float4 layout (combine is layout-agnostic)
    float4* G4 = (float4*)g_G + ((size_t)(split * NTILES + blk)) * 1024;
    #pragma unroll
    for (int mi = 0; mi < 2; mi++)
        #pragma unroll
        for (int ni = 0; ni < 2; ni++) {
            int f = mi * 2 + ni;
            G4[f * 256 + t] = make_float4(acc[mi][ni][0], acc[mi][ni][1],
                                          acc[mi][ni][2], acc[mi][ni][3]);
        }
}

// ---------------------------------------------------------------------------
// Kernel 3: combine splits, square, signed reduce, fused finalize.
// ---------------------------------------------------------------------------
__global__ void __launch_bounds__(256) combine_kernel(float* __restrict__ out) {
    __shared__ float sred[8];
    __shared__ unsigned int s_last;
    int t = threadIdx.x, lane = t & 31, wid = t >> 5;
    int blk = blockIdx.x;

    int a = 0, rem = blk, rl = NT;
    while (rem >= rl) { rem -= rl; a++; rl--; }
    int b2 = a + rem;

    const float4* G4 = (const float4*)g_G;
    size_t o0 = (size_t)blk * 1024;
    size_t o1 = (size_t)(NTILES + blk) * 1024;

    float sum = 0.f;
    #pragma unroll
    for (int f = 0; f < 4; f++) {
        float4 u = G4[o0 + f * 256 + t];
        float4 v = G4[o1 + f * 256 + t];
        float x = u.x + v.x, y = u.y + v.y, z = u.z + v.z, w = u.w + v.w;
        sum += x * x + y * y + z * z + w * w;
    }
    #pragma unroll
    for (int o = 16; o > 0; o >>= 1)
        sum += __shfl_xor_sync(0xFFFFFFFFu, sum, o);
    if (lane == 0) sred[wid] = sum;
    __syncthreads();
    if (t == 0) {
        float tot = 0.f;
        #pragma unroll
        for (int i = 0; i < 8; i++) tot += sred[i];
        float sp = ((a < 2) != (b2 < 2)) ? -1.f : 1.f;
        float w  = sp * ((a == b2) ? 1.f : 2.f);
        g_part[blk] = w * tot;
        __threadfence();
        s_last = (atomicAdd(&g_count, 1u) == NTILES - 1);
    }
    __syncthreads();

    if (s_last) {
        __shared__ float fs[256];
        fs[t] = (t < NTILES) ? g_part[t] : 0.f;
        __syncthreads();
        #pragma unroll
        for (int o = 128; o > 0; o >>= 1) {
            if (t < o) fs[t] += fs[t + o];
            __syncthreads();
        }
        if (t == 0) {
            out[0] = fs[0] / ((float)N_SAMPLES * (float)(N_SAMPLES - 1));
            g_count = 0;
        }
    }
}

// ---------------------------------------------------------------------------
extern "C" void kernel_launch(void* const* d_in, const int* in_sizes, int n_in,
                              void* d_out, int out_size) {
    const float* red;
    const float* full;
    if (in_sizes[0] == N_SAMPLES * D_RED) {
        red  = (const float*)d_in[0];
        full = (const float*)d_in[1];
    } else {
        red  = (const float*)d_in[1];
        full = (const float*)d_in[0];
    }

    static int attr_done = 0;
    if (!attr_done) {
        cudaFuncSetAttribute(gram_kernel, cudaFuncAttributeMaxDynamicSharedMemorySize,
                             GSMEM);
        attr_done = 1;
    }

    normalize_kernel<<<N_SAMPLES / 8, 256>>>(red, full);
    gram_kernel<<<dim3(NTILES, NSPLIT), 256, GSMEM>>>();
    combine_kernel<<<NTILES, 256>>>((float*)d_out);
}

// round 7
// speedup vs baseline: 5.4275x; 1.1400x over previous
#include <cuda_runtime.h>
#include <cuda_bf16.h>
#include <cstdint>

// ContrastiveCosineLoss via signed feature-Gram SYRK on warp-level bf16 MMA.
// Round 7: 32x32 warp tiles with intra-CTA k-split (2 k-half warp groups,
// SMEM merge), 2-warps-per-row normalize. Split-K=2 across CTAs + combine.

#define N_SAMPLES 2048
#define D_RED     128
#define D_TOT     1152                 // 18 * 64
#define TILE      64
#define NT        (D_TOT / TILE)       // 18
#define NTILES    (NT * (NT + 1) / 2)  // 171
#define NSPLIT    2
#define KSPLIT    (N_SAMPLES / NSPLIT) // 1024
#define CHUNK     64
#define NCHUNK_S  (KSPLIT / CHUNK)     // 16
#define PITCH     72                   // bf16 per SMEM row (144B: LDSM.T bank-safe)
#define STAGES    3
#define SLABB     (CHUNK * PITCH * 2)  // 9216 B per operand slab
#define GSMEM     (STAGES * 2 * SLABB) // 55296 B dynamic smem

__device__ __align__(4096) __nv_bfloat16 g_Yb[N_SAMPLES * D_TOT];
__device__ __align__(4096) float g_G[NSPLIT * NTILES * TILE * TILE]; // partial Gram
__device__ float g_part[NTILES];
__device__ unsigned int g_count;

// ---------------------------------------------------------------------------
__device__ __forceinline__ uint32_t smem_u32(const void* p) {
    uint32_t a;
    asm("{ .reg .u64 t; cvta.to.shared.u64 t, %1; cvt.u32.u64 %0, t; }" : "=r"(a) : "l"(p));
    return a;
}
__device__ __forceinline__ void cp16(uint32_t sdst, const void* g) {
    asm volatile("cp.async.cg.shared.global [%0], [%1], 16;" :: "r"(sdst), "l"(g) : "memory");
}
__device__ __forceinline__ void ldsm_x4_t(uint32_t* r, uint32_t addr) {
    asm volatile("ldmatrix.sync.aligned.m8n8.x4.trans.shared.b16 {%0,%1,%2,%3}, [%4];"
                 : "=r"(r[0]), "=r"(r[1]), "=r"(r[2]), "=r"(r[3]) : "r"(addr));
}
__device__ __forceinline__ void mma_bf16(float* c, const uint32_t* a, uint32_t b0, uint32_t b1) {
    asm volatile(
        "mma.sync.aligned.m16n8k16.row.col.f32.bf16.bf16.f32 "
        "{%0,%1,%2,%3}, {%4,%5,%6,%7}, {%8,%9}, {%0,%1,%2,%3};"
        : "+f"(c[0]), "+f"(c[1]), "+f"(c[2]), "+f"(c[3])
        : "r"(a[0]), "r"(a[1]), "r"(a[2]), "r"(a[3]), "r"(b0), "r"(b1));
}

// ---------------------------------------------------------------------------
// Kernel 1: row-normalize -> bf16 row-major. TWO warps per sample row.
// grid = 512 blocks x 256 threads (8 warps = 4 rows).
// ---------------------------------------------------------------------------
__global__ void __launch_bounds__(256) normalize_kernel(const float* __restrict__ red,
                                                        const float* __restrict__ full) {
    int t = threadIdx.x, lane = t & 31, wid = t >> 5;
    int r = wid >> 1, half = wid & 1;
    int row = blockIdx.x * 4 + r;

    const float4* f4 = (const float4*)(full + (size_t)row * 1024);
    const float4* r4 = (const float4*)(red  + (size_t)row * D_RED);

    float4 fv[4];
    #pragma unroll
    for (int j = 0; j < 4; j++) fv[j] = f4[half * 128 + lane + 32 * j];

    float sf = 0.f;
    #pragma unroll
    for (int j = 0; j < 4; j++)
        sf += fv[j].x * fv[j].x + fv[j].y * fv[j].y + fv[j].z * fv[j].z + fv[j].w * fv[j].w;

    float4 rv = make_float4(0.f, 0.f, 0.f, 0.f);
    float sr = 0.f;
    if (half == 0) {
        rv = r4[lane];
        sr = rv.x * rv.x + rv.y * rv.y + rv.z * rv.z + rv.w * rv.w;
    }

    #pragma unroll
    for (int o = 16; o > 0; o >>= 1) {
        sf += __shfl_xor_sync(0xFFFFFFFFu, sf, o);
        sr += __shfl_xor_sync(0xFFFFFFFFu, sr, o);
    }

    __shared__ float sF[8], sR[4];
    if (lane == 0) { sF[wid] = sf; if (half == 0) sR[r] = sr; }
    __syncthreads();

    float iff = 1.f / fmaxf(sqrtf(sF[2 * r] + sF[2 * r + 1]), 1e-8f);
    float ir  = 1.f / fmaxf(sqrtf(sR[r]), 1e-8f);

    if (half == 0) {
        __nv_bfloat162 h0 = __floats2bfloat162_rn(rv.x * ir, rv.y * ir);
        __nv_bfloat162 h1 = __floats2bfloat162_rn(rv.z * ir, rv.w * ir);
        ((uint2*)(g_Yb + (size_t)row * D_TOT))[lane] =
            make_uint2(*(uint32_t*)&h0, *(uint32_t*)&h1);
    }
    uint2* dst = (uint2*)(g_Yb + (size_t)row * D_TOT + D_RED);
    #pragma unroll
    for (int j = 0; j < 4; j++) {
        __nv_bfloat162 h0 = __floats2bfloat162_rn(fv[j].x * iff, fv[j].y * iff);
        __nv_bfloat162 h1 = __floats2bfloat162_rn(fv[j].z * iff, fv[j].w * iff);
        dst[half * 128 + lane + 32 * j] = make_uint2(*(uint32_t*)&h0, *(uint32_t*)&h1);
    }
}

// ---------------------------------------------------------------------------
// Kernel 2: bf16 warp-MMA partial SYRK tile (K split). 8 warps:
//   quadrant wq = wid&3 -> 32x32 output block; k-half kh = wid>>2 -> 32 of 64
//   chunk samples. k-halves merged via SMEM at the end; writes partial Gram.
// grid = (NTILES, NSPLIT), 256 threads.
// ---------------------------------------------------------------------------
__global__ void __launch_bounds__(256, 2) gram_kernel() {
    extern __shared__ __align__(16) char dyn[];
    int t = threadIdx.x, lane = t & 31, wid = t >> 5;

    int blk = blockIdx.x, split = blockIdx.y;
    int a = 0, rem = blk, rl = NT;
    while (rem >= rl) { rem -= rl; a++; rl--; }
    int b2 = a + rem;

    // ---- hoisted cp.async addressing (4 x 16B per thread per chunk) ----
    int lrowg = t >> 3;            // 0..31 (j=0), +32 for j=1
    int lv    = (t & 7) * 8;       // bf16 offset of 16B segment
    uint32_t sA0 = smem_u32(dyn) + (uint32_t)(lrowg * PITCH + lv) * 2;
    uint32_t sB0 = sA0 + SLABB;
    const uint32_t rowStep = 32 * PITCH * 2;
    const __nv_bfloat16* gA0 = g_Yb + (size_t)(split * KSPLIT + lrowg) * D_TOT + a * TILE + lv;
    const __nv_bfloat16* gB0 = g_Yb + (size_t)(split * KSPLIT + lrowg) * D_TOT + b2 * TILE + lv;
    const size_t gRow = (size_t)32 * D_TOT;
    const size_t gChunk = (size_t)CHUNK * D_TOT;

    auto load_chunk = [&](int s, int c) {
        uint32_t so = (uint32_t)(s * 2 * SLABB);
        const __nv_bfloat16* ga = gA0 + c * gChunk;
        const __nv_bfloat16* gb = gB0 + c * gChunk;
        cp16(sA0 + so,           ga);
        cp16(sA0 + so + rowStep, ga + gRow);
        cp16(sB0 + so,           gb);
        cp16(sB0 + so + rowStep, gb + gRow);
    };

    // ---- warp tiling: 2x2 quadrants x 2 k-halves ----
    int wq = wid & 3, kh = wid >> 2;
    int m0 = (wq & 1) * 32;
    int n0 = (wq >> 1) * 32;
    int lrow = (lane & 7) + ((lane >> 4) & 1) * 8;
    int lcol = ((lane >> 3) & 1) * 8;
    uint32_t base = smem_u32(dyn);
    // A addresses: k-row = kh*32 + ks*16 + lrow ; cols m0+lcol (+16)
    uint32_t aA = base + (uint32_t)((kh * 32 + lrow) * PITCH + m0 + lcol) * 2;
    uint32_t aB = base + SLABB + (uint32_t)((kh * 32 + lrow) * PITCH + n0 + lcol) * 2;
    const uint32_t kStep = 16 * PITCH * 2;

    float acc[2][4][4] = {};   // [m16][n8][frag]

    load_chunk(0, 0);
    asm volatile("cp.async.commit_group;" ::: "memory");
    load_chunk(1, 1);
    asm volatile("cp.async.commit_group;" ::: "memory");

    int s = 0;
    for (int c = 0; c < NCHUNK_S; c++) {
        asm volatile("cp.async.wait_group 1;" ::: "memory");
        __syncthreads();

        if (c + 2 < NCHUNK_S) {
            int s2 = s + 2; if (s2 >= STAGES) s2 -= STAGES;
            load_chunk(s2, c + 2);
        }
        asm volatile("cp.async.commit_group;" ::: "memory");

        uint32_t so = (uint32_t)(s * 2 * SLABB);
        // batch all fragment loads for both ks steps, then all MMAs
        uint32_t af[2][2][4], bf[2][2][4];
        #pragma unroll
        for (int ks = 0; ks < 2; ks++) {
            uint32_t ko = so + ks * kStep;
            ldsm_x4_t(af[ks][0], aA + ko);
            ldsm_x4_t(af[ks][1], aA + ko + 32);        // +16 m cols
            ldsm_x4_t(bf[ks][0], aB + ko);
            ldsm_x4_t(bf[ks][1], aB + ko + 32);        // +16 n cols
        }
        #pragma unroll
        for (int ks = 0; ks < 2; ks++)
            #pragma unroll
            for (int mi = 0; mi < 2; mi++) {
                mma_bf16(acc[mi][0], af[ks][mi], bf[ks][0][0], bf[ks][0][2]);
                mma_bf16(acc[mi][1], af[ks][mi], bf[ks][0][1], bf[ks][0][3]);
                mma_bf16(acc[mi][2], af[ks][mi], bf[ks][1][0], bf[ks][1][2]);
                mma_bf16(acc[mi][3], af[ks][mi], bf[ks][1][1], bf[ks][1][3]);
            }
        if (++s >= STAGES) s -= STAGES;
    }

    // ---- merge k-halves via SMEM (reuse pipeline smem), write partial Gram ----
    __syncthreads();
    float4* M4 = (float4*)dyn;                 // 8 float4 x 128 threads = 16 KB
    int tt = wq * 32 + lane;                   // 0..127 within k-half group
    if (kh == 1) {
        #pragma unroll
        for (int mi = 0; mi < 2; mi++)
            #pragma unroll
            for (int ni = 0; ni < 4; ni++)
                M4[(mi * 4 + ni) * 128 + tt] =
                    make_float4(acc[mi][ni][0], acc[mi][ni][1],
                                acc[mi][ni][2], acc[mi][ni][3]);
    }
    __syncthreads();
    if (kh == 0) {
        float4* G4 = (float4*)g_G + ((size_t)(split * NTILES + blk)) * 1024;
        #pragma unroll
        for (int mi = 0; mi < 2; mi++)
            #pragma unroll
            for (int ni = 0; ni < 4; ni++) {
                int f = mi * 4 + ni;
                float4 v = M4[f * 128 + tt];
                G4[f * 128 + tt] = make_float4(acc[mi][ni][0] + v.x,
                                               acc[mi][ni][1] + v.y,
                                               acc[mi][ni][2] + v.z,
                                               acc[mi][ni][3] + v.w);
            }
    }
}

// ---------------------------------------------------------------------------
// Kernel 3: combine splits, square, signed reduce, fused finalize.
// ---------------------------------------------------------------------------
__global__ void __launch_bounds__(256) combine_kernel(float* __restrict__ out) {
    __shared__ float sred[8];
    __shared__ unsigned int s_last;
    int t = threadIdx.x, lane = t & 31, wid = t >> 5;
    int blk = blockIdx.x;

    int a = 0, rem = blk, rl = NT;
    while (rem >= rl) { rem -= rl; a++; rl--; }
    int b2 = a + rem;

    const float4* G4 = (const float4*)g_G;
    size_t o0 = (size_t)blk * 1024;
    size_t o1 = (size_t)(NTILES + blk) * 1024;

    float sum = 0.f;
    #pragma unroll
    for (int f = 0; f < 4; f++) {
        float4 u = G4[o0 + f * 256 + t];
        float4 v = G4[o1 + f * 256 + t];
        float x = u.x + v.x, y = u.y + v.y, z = u.z + v.z, w = u.w + v.w;
        sum += x * x + y * y + z * z + w * w;
    }
    #pragma unroll
    for (int o = 16; o > 0; o >>= 1)
        sum += __shfl_xor_sync(0xFFFFFFFFu, sum, o);
    if (lane == 0) sred[wid] = sum;
    __syncthreads();
    if (t == 0) {
        float tot = 0.f;
        #pragma unroll
        for (int i = 0; i < 8; i++) tot += sred[i];
        float sp = ((a < 2) != (b2 < 2)) ? -1.f : 1.f;
        float w  = sp * ((a == b2) ? 1.f : 2.f);
        g_part[blk] = w * tot;
        __threadfence();
        s_last = (atomicAdd(&g_count, 1u) == NTILES - 1);
    }
    __syncthreads();

    if (s_last) {
        __shared__ float fs[256];
        fs[t] = (t < NTILES) ? g_part[t] : 0.f;
        __syncthreads();
        #pragma unroll
        for (int o = 128; o > 0; o >>= 1) {
            if (t < o) fs[t] += fs[t + o];
            __syncthreads();
        }
        if (t == 0) {
            out[0] = fs[0] / ((float)N_SAMPLES * (float)(N_SAMPLES - 1));
            g_count = 0;
        }
    }
}

// ---------------------------------------------------------------------------
extern "C" void kernel_launch(void* const* d_in, const int* in_sizes, int n_in,
                              void* d_out, int out_size) {
    const float* red;
    const float* full;
    if (in_sizes[0] == N_SAMPLES * D_RED) {
        red  = (const float*)d_in[0];
        full = (const float*)d_in[1];
    } else {
        red  = (const float*)d_in[1];
        full = (const float*)d_in[0];
    }

    static int attr_done = 0;
    if (!attr_done) {
        cudaFuncSetAttribute(gram_kernel, cudaFuncAttributeMaxDynamicSharedMemorySize,
                             GSMEM);
        attr_done = 1;
    }

    normalize_kernel<<<N_SAMPLES / 4, 256>>>(red, full);
    gram_kernel<<<dim3(NTILES, NSPLIT), 256, GSMEM>>>();
    combine_kernel<<<NTILES, 256>>>((float*)d_out);
}

// round 8
// speedup vs baseline: 5.4968x; 1.0128x over previous
#include <cuda_runtime.h>
#include <cuda_bf16.h>
#include <cstdint>

// ContrastiveCosineLoss via signed feature-Gram SYRK on warp-level bf16 MMA.
// Round 8: split-K=4 (684 CTAs), per-tile decoupled combine fused into gram
// (threadfence + atomic tile counters, deterministic fixed-order sums),
// global finalize by last tile-combiner. Two launches total.

#define N_SAMPLES 2048
#define D_RED     128
#define D_TOT     1152                 // 18 * 64
#define TILE      64
#define NT        (D_TOT / TILE)       // 18
#define NTILES    (NT * (NT + 1) / 2)  // 171
#define NSPLIT    4
#define KSPLIT    (N_SAMPLES / NSPLIT) // 512
#define CHUNK     64
#define NCHUNK_S  (KSPLIT / CHUNK)     // 8
#define PITCH     72                   // bf16 per SMEM row (144B: LDSM.T bank-safe)
#define STAGES    3
#define SLABB     (CHUNK * PITCH * 2)  // 9216 B per operand slab
#define GSMEM     (STAGES * 2 * SLABB) // 55296 B dynamic smem

__device__ __align__(4096) __nv_bfloat16 g_Yb[N_SAMPLES * D_TOT];
__device__ __align__(4096) float g_G[NSPLIT * NTILES * TILE * TILE];
__device__ float g_part[NTILES];
__device__ unsigned int g_tile_count[NTILES];  // zero-init; self-resetting
__device__ unsigned int g_count;               // zero-init; self-resetting

// ---------------------------------------------------------------------------
__device__ __forceinline__ uint32_t smem_u32(const void* p) {
    uint32_t a;
    asm("{ .reg .u64 t; cvta.to.shared.u64 t, %1; cvt.u32.u64 %0, t; }" : "=r"(a) : "l"(p));
    return a;
}
__device__ __forceinline__ void cp16(uint32_t sdst, const void* g) {
    asm volatile("cp.async.cg.shared.global [%0], [%1], 16;" :: "r"(sdst), "l"(g) : "memory");
}
__device__ __forceinline__ void ldsm_x4_t(uint32_t* r, uint32_t addr) {
    asm volatile("ldmatrix.sync.aligned.m8n8.x4.trans.shared.b16 {%0,%1,%2,%3}, [%4];"
                 : "=r"(r[0]), "=r"(r[1]), "=r"(r[2]), "=r"(r[3]) : "r"(addr));
}
__device__ __forceinline__ void mma_bf16(float* c, const uint32_t* a, uint32_t b0, uint32_t b1) {
    asm volatile(
        "mma.sync.aligned.m16n8k16.row.col.f32.bf16.bf16.f32 "
        "{%0,%1,%2,%3}, {%4,%5,%6,%7}, {%8,%9}, {%0,%1,%2,%3};"
        : "+f"(c[0]), "+f"(c[1]), "+f"(c[2]), "+f"(c[3])
        : "r"(a[0]), "r"(a[1]), "r"(a[2]), "r"(a[3]), "r"(b0), "r"(b1));
}

// ---------------------------------------------------------------------------
// Kernel 1: row-normalize -> bf16 row-major. One warp per sample row, MLP 8.
// ---------------------------------------------------------------------------
__global__ void __launch_bounds__(256) normalize_kernel(const float* __restrict__ red,
                                                        const float* __restrict__ full) {
    int t = threadIdx.x, lane = t & 31, wid = t >> 5;
    int row = blockIdx.x * 8 + wid;

    const float4* f4 = (const float4*)(full + (size_t)row * 1024);
    const float4* r4 = (const float4*)(red  + (size_t)row * D_RED);

    float4 fv[8];
    #pragma unroll
    for (int j = 0; j < 8; j++) fv[j] = f4[lane + 32 * j];
    float4 rv = r4[lane];

    float sf = 0.f;
    #pragma unroll
    for (int j = 0; j < 8; j++)
        sf += fv[j].x * fv[j].x + fv[j].y * fv[j].y + fv[j].z * fv[j].z + fv[j].w * fv[j].w;
    float sr = rv.x * rv.x + rv.y * rv.y + rv.z * rv.z + rv.w * rv.w;

    #pragma unroll
    for (int o = 16; o > 0; o >>= 1) {
        sf += __shfl_xor_sync(0xFFFFFFFFu, sf, o);
        sr += __shfl_xor_sync(0xFFFFFFFFu, sr, o);
    }
    float iff = 1.f / fmaxf(sqrtf(sf), 1e-8f);
    float ir  = 1.f / fmaxf(sqrtf(sr), 1e-8f);

    {
        __nv_bfloat162 h0 = __floats2bfloat162_rn(rv.x * ir, rv.y * ir);
        __nv_bfloat162 h1 = __floats2bfloat162_rn(rv.z * ir, rv.w * ir);
        ((uint2*)(g_Yb + (size_t)row * D_TOT))[lane] =
            make_uint2(*(uint32_t*)&h0, *(uint32_t*)&h1);
    }
    uint2* dst = (uint2*)(g_Yb + (size_t)row * D_TOT + D_RED);
    #pragma unroll
    for (int j = 0; j < 8; j++) {
        __nv_bfloat162 h0 = __floats2bfloat162_rn(fv[j].x * iff, fv[j].y * iff);
        __nv_bfloat162 h1 = __floats2bfloat162_rn(fv[j].z * iff, fv[j].w * iff);
        dst[lane + 32 * j] = make_uint2(*(uint32_t*)&h0, *(uint32_t*)&h1);
    }
}

// ---------------------------------------------------------------------------
// Kernel 2: bf16 warp-MMA partial SYRK (split-K=4) + decoupled per-tile
// combine + global finalize. grid = (NTILES, NSPLIT), 256 threads.
// ---------------------------------------------------------------------------
__global__ void __launch_bounds__(256, 2) gram_kernel(float* __restrict__ out) {
    extern __shared__ __align__(16) char dyn[];
    __shared__ float sred[8];
    __shared__ unsigned int s_comb, s_last;

    int t = threadIdx.x, lane = t & 31, wid = t >> 5;

    int blk = blockIdx.x, split = blockIdx.y;
    int a = 0, rem = blk, rl = NT;
    while (rem >= rl) { rem -= rl; a++; rl--; }
    int b2 = a + rem;

    // ---- hoisted cp.async addressing ----
    int lrowg = t >> 3;
    int lv    = (t & 7) * 8;
    uint32_t sA0 = smem_u32(dyn) + (uint32_t)(lrowg * PITCH + lv) * 2;
    uint32_t sB0 = sA0 + SLABB;
    const uint32_t rowStep = 32 * PITCH * 2;
    const __nv_bfloat16* gA0 = g_Yb + (size_t)(split * KSPLIT + lrowg) * D_TOT + a * TILE + lv;
    const __nv_bfloat16* gB0 = g_Yb + (size_t)(split * KSPLIT + lrowg) * D_TOT + b2 * TILE + lv;
    const size_t gRow = (size_t)32 * D_TOT;
    const size_t gChunk = (size_t)CHUNK * D_TOT;

    auto load_chunk = [&](int s, int c) {
        uint32_t so = (uint32_t)(s * 2 * SLABB);
        const __nv_bfloat16* ga = gA0 + c * gChunk;
        const __nv_bfloat16* gb = gB0 + c * gChunk;
        cp16(sA0 + so,           ga);
        cp16(sA0 + so + rowStep, ga + gRow);
        cp16(sB0 + so,           gb);
        cp16(sB0 + so + rowStep, gb + gRow);
    };

    // ---- warp tiling: 2x2 quadrants x 2 k-halves ----
    int wq = wid & 3, kh = wid >> 2;
    int m0 = (wq & 1) * 32;
    int n0 = (wq >> 1) * 32;
    int lrow = (lane & 7) + ((lane >> 4) & 1) * 8;
    int lcol = ((lane >> 3) & 1) * 8;
    uint32_t base = smem_u32(dyn);
    uint32_t aA = base + (uint32_t)((kh * 32 + lrow) * PITCH + m0 + lcol) * 2;
    uint32_t aB = base + SLABB + (uint32_t)((kh * 32 + lrow) * PITCH + n0 + lcol) * 2;
    const uint32_t kStep = 16 * PITCH * 2;

    float acc[2][4][4] = {};

    load_chunk(0, 0);
    asm volatile("cp.async.commit_group;" ::: "memory");
    load_chunk(1, 1);
    asm volatile("cp.async.commit_group;" ::: "memory");

    int s = 0;
    for (int c = 0; c < NCHUNK_S; c++) {
        asm volatile("cp.async.wait_group 1;" ::: "memory");
        __syncthreads();

        if (c + 2 < NCHUNK_S) {
            int s2 = s + 2; if (s2 >= STAGES) s2 -= STAGES;
            load_chunk(s2, c + 2);
        }
        asm volatile("cp.async.commit_group;" ::: "memory");

        uint32_t so = (uint32_t)(s * 2 * SLABB);
        uint32_t af[2][2][4], bf[2][2][4];
        #pragma unroll
        for (int ks = 0; ks < 2; ks++) {
            uint32_t ko = so + ks * kStep;
            ldsm_x4_t(af[ks][0], aA + ko);
            ldsm_x4_t(af[ks][1], aA + ko + 32);
            ldsm_x4_t(bf[ks][0], aB + ko);
            ldsm_x4_t(bf[ks][1], aB + ko + 32);
        }
        #pragma unroll
        for (int ks = 0; ks < 2; ks++)
            #pragma unroll
            for (int mi = 0; mi < 2; mi++) {
                mma_bf16(acc[mi][0], af[ks][mi], bf[ks][0][0], bf[ks][0][2]);
                mma_bf16(acc[mi][1], af[ks][mi], bf[ks][0][1], bf[ks][0][3]);
                mma_bf16(acc[mi][2], af[ks][mi], bf[ks][1][0], bf[ks][1][2]);
                mma_bf16(acc[mi][3], af[ks][mi], bf[ks][1][1], bf[ks][1][3]);
            }
        if (++s >= STAGES) s -= STAGES;
    }

    // ---- merge k-halves via SMEM, write partial Gram ----
    __syncthreads();
    float4* M4 = (float4*)dyn;
    int tt = wq * 32 + lane;
    if (kh == 1) {
        #pragma unroll
        for (int mi = 0; mi < 2; mi++)
            #pragma unroll
            for (int ni = 0; ni < 4; ni++)
                M4[(mi * 4 + ni) * 128 + tt] =
                    make_float4(acc[mi][ni][0], acc[mi][ni][1],
                                acc[mi][ni][2], acc[mi][ni][3]);
    }
    __syncthreads();
    if (kh == 0) {
        float4* G4 = (float4*)g_G + ((size_t)(split * NTILES + blk)) * 1024;
        #pragma unroll
        for (int mi = 0; mi < 2; mi++)
            #pragma unroll
            for (int ni = 0; ni < 4; ni++) {
                int f = mi * 4 + ni;
                float4 v = M4[f * 128 + tt];
                G4[f * 128 + tt] = make_float4(acc[mi][ni][0] + v.x,
                                               acc[mi][ni][1] + v.y,
                                               acc[mi][ni][2] + v.z,
                                               acc[mi][ni][3] + v.w);
            }
    }

    // ---- decoupled per-tile combine (threadFenceReduction pattern) ----
    __syncthreads();
    if (t == 0) {
        __threadfence();
        s_comb = (atomicAdd(&g_tile_count[blk], 1u) == NSPLIT - 1);
    }
    __syncthreads();
    if (!s_comb) return;

    __threadfence();   // acquire partials written by sibling CTAs
    {
        const float4* G4 = (const float4*)g_G;
        float sum = 0.f;
        #pragma unroll
        for (int f = 0; f < 4; f++) {
            size_t idx = (size_t)blk * 1024 + f * 256 + t;
            float x = 0.f, y = 0.f, z = 0.f, w = 0.f;
            #pragma unroll
            for (int sp = 0; sp < NSPLIT; sp++) {   // fixed order: deterministic
                float4 u = G4[(size_t)sp * NTILES * 1024 + idx];
                x += u.x; y += u.y; z += u.z; w += u.w;
            }
            sum += x * x + y * y + z * z + w * w;
        }
        #pragma unroll
        for (int o = 16; o > 0; o >>= 1)
            sum += __shfl_xor_sync(0xFFFFFFFFu, sum, o);
        if (lane == 0) sred[wid] = sum;
    }
    __syncthreads();
    if (t == 0) {
        float tot = 0.f;
        #pragma unroll
        for (int i = 0; i < 8; i++) tot += sred[i];
        float sp = ((a < 2) != (b2 < 2)) ? -1.f : 1.f;
        float w  = sp * ((a == b2) ? 1.f : 2.f);
        g_part[blk] = w * tot;
        g_tile_count[blk] = 0;     // reset for next graph replay
        __threadfence();
        s_last = (atomicAdd(&g_count, 1u) == NTILES - 1);
    }
    __syncthreads();

    // ---- global finalize by last tile-combiner ----
    if (s_last) {
        __threadfence();
        __shared__ float fs[256];
        fs[t] = (t < NTILES) ? g_part[t] : 0.f;
        __syncthreads();
        #pragma unroll
        for (int o = 128; o > 0; o >>= 1) {
            if (t < o) fs[t] += fs[t + o];
            __syncthreads();
        }
        if (t == 0) {
            out[0] = fs[0] / ((float)N_SAMPLES * (float)(N_SAMPLES - 1));
            g_count = 0;           // reset for next graph replay
        }
    }
}

// ---------------------------------------------------------------------------
extern "C" void kernel_launch(void* const* d_in, const int* in_sizes, int n_in,
                              void* d_out, int out_size) {
    const float* red;
    const float* full;
    if (in_sizes[0] == N_SAMPLES * D_RED) {
        red  = (const float*)d_in[0];
        full = (const float*)d_in[1];
    } else {
        red  = (const float*)d_in[1];
        full = (const float*)d_in[0];
    }

    static int attr_done = 0;
    if (!attr_done) {
        cudaFuncSetAttribute(gram_kernel, cudaFuncAttributeMaxDynamicSharedMemorySize,
                             GSMEM);
        attr_done = 1;
    }

    normalize_kernel<<<N_SAMPLES / 8, 256>>>(red, full);
    gram_kernel<<<dim3(NTILES, NSPLIT), 256, GSMEM>>>((float*)d_out);
}